// round 8
// baseline (speedup 1.0000x reference)
#include <cuda_runtime.h>
#include <cuda_fp16.h>

#define N_NODES 100000
#define N_EDGES 3200000
#define IN_DIM  128
#define HID     64

#define SCAN_B  512
#define SCAN_NB ((N_NODES + SCAN_B - 1) / SCAN_B)   // 196
#define PREP_NB ((N_NODES + 255) / 256)             // 391

// ---------------- scratch (device globals; no allocation allowed) ----------------
__device__ int     g_is64;                  // 1 if edge_index is int64, 0 if int32
__device__ int     g_deg[N_NODES];
__device__ float   g_dinv[N_NODES];
__device__ int     g_rowptr[N_NODES + 1];
__device__ int     g_cursor[N_NODES];
__device__ int     g_scan[N_NODES];
__device__ int     g_bsum[SCAN_NB];
__device__ int     g_boff[SCAN_NB];
__device__ int     g_csr[N_EDGES];          // src index only
__device__ __half2 g_h1h[N_NODES * (HID/2)];// h1' = dinv * (x @ W1^T), fp16
__device__ float   g_z[N_NODES];            // z'  = dinv * (a1 . w)
__device__ float   g_w[HID];                // w = W2^T @ Wc
__device__ float   g_cb;                    // b2.Wc + bc

// ---------------- prep: deg init + dtype probe + classifier fold ----------------
__global__ void prep_kernel(const unsigned* __restrict__ ei32,
                            const float* __restrict__ W2, const float* __restrict__ b2,
                            const float* __restrict__ Wc, const float* __restrict__ bc) {
    int b = blockIdx.x, tid = threadIdx.x;
    if (b < PREP_NB) {
        int i = b * 256 + tid;
        if (i < N_NODES) g_deg[i] = 1;          // self-loop counts as 1
    } else if (b == PREP_NB) {
        if (tid == 0) {
            // int64 ids in [0,100000) => every odd 32-bit word is 0.
            unsigned o = 0;
            #pragma unroll
            for (int i = 1; i < 128; i += 2) o |= ei32[i];
            g_is64 = (o == 0) ? 1 : 0;
        }
    } else {
        if (tid < HID) {
            float s = 0.f;
            #pragma unroll
            for (int j = 0; j < HID; j++) s = fmaf(Wc[j], W2[j * HID + tid], s);
            g_w[tid] = s;
            if (tid == 0) {
                float c = bc[0];
                #pragma unroll
                for (int j = 0; j < HID; j++) c = fmaf(b2[j], Wc[j], c);
                g_cb = c;
            }
        }
    }
}

// ---------------- load 4 consecutive edge ids ----------------
__device__ __forceinline__ void edge4(const void* ei, long long base, int* v) {
    if (g_is64) {
        longlong4 a = *(const longlong4*)((const long long*)ei + base);
        v[0] = (int)a.x; v[1] = (int)a.y; v[2] = (int)a.z; v[3] = (int)a.w;
    } else {
        int4 a = *(const int4*)((const int*)ei + base);
        v[0] = a.x; v[1] = a.y; v[2] = a.z; v[3] = a.w;
    }
}

// ---------------- dst-degree histogram (4 edges/thread) ----------------
__global__ void hist_kernel(const void* __restrict__ ei) {
    long long e0 = (long long)(blockIdx.x * 256 + threadIdx.x) * 4;
    int d[4];
    edge4(ei, (long long)N_EDGES + e0, d);
    #pragma unroll
    for (int j = 0; j < 4; j++) atomicAdd(&g_deg[d[j]], 1);
}

// ---------------- parallel 3-phase exclusive scan of (deg-1) ----------------
__global__ void scan1_kernel() {
    __shared__ int wsum[16];
    const int tid  = threadIdx.x;
    const int lane = tid & 31, warp = tid >> 5;
    const int i = blockIdx.x * SCAN_B + tid;
    int v = (i < N_NODES) ? (g_deg[i] - 1) : 0;
    int s = v;
    #pragma unroll
    for (int o = 1; o < 32; o <<= 1) {
        int t = __shfl_up_sync(0xffffffffu, s, o);
        if (lane >= o) s += t;
    }
    if (lane == 31) wsum[warp] = s;
    __syncthreads();
    if (warp == 0) {
        int ws = (lane < 16) ? wsum[lane] : 0;
        #pragma unroll
        for (int o = 1; o < 16; o <<= 1) {
            int t = __shfl_up_sync(0xffffffffu, ws, o);
            if (lane >= o) ws += t;
        }
        if (lane < 16) wsum[lane] = ws;
    }
    __syncthreads();
    int excl = s - v + (warp ? wsum[warp - 1] : 0);
    if (i < N_NODES) g_scan[i] = excl;
    if (tid == SCAN_B - 1) g_bsum[blockIdx.x] = excl + v;
}

__global__ void scan2_kernel() {       // 1 block, 256 threads (>=196)
    __shared__ int sh[256];
    const int t = threadIdx.x;
    int v0 = (t < SCAN_NB) ? g_bsum[t] : 0;
    sh[t] = v0;
    __syncthreads();
    #pragma unroll
    for (int o = 1; o < 256; o <<= 1) {
        int v = (t >= o) ? sh[t - o] : 0;
        __syncthreads();
        sh[t] += v;
        __syncthreads();
    }
    if (t < SCAN_NB) g_boff[t] = sh[t] - v0;
}

__global__ void scan3_kernel() {
    int i = blockIdx.x * blockDim.x + threadIdx.x;
    if (i < N_NODES) {
        int off = g_scan[i] + g_boff[i / SCAN_B];
        g_rowptr[i] = off;
        g_cursor[i] = off;
        g_dinv[i]   = rsqrtf((float)g_deg[i]);
    }
    if (i == 0) g_rowptr[N_NODES] = N_EDGES;   // sum(deg-1) == E
}

// ---------------- counting-sort scatter: CSR of src indices (4 edges/thread) ----------------
__global__ void scatter_kernel(const void* __restrict__ ei) {
    long long e0 = (long long)(blockIdx.x * 256 + threadIdx.x) * 4;
    int s[4], d[4];
    edge4(ei, e0, s);
    edge4(ei, (long long)N_EDGES + e0, d);
    #pragma unroll
    for (int j = 0; j < 4; j++) {
        int pos = atomicAdd(&g_cursor[d[j]], 1);
        g_csr[pos] = s[j];
    }
}

// ---------------- tf32 helpers ----------------
__device__ __forceinline__ unsigned f2tf(float f) {
    unsigned u;
    asm("cvt.rna.tf32.f32 %0, %1;" : "=r"(u) : "f"(f));
    return u;
}

__device__ __forceinline__ void mma_tf32(float* c,
                                         unsigned a0, unsigned a1, unsigned a2, unsigned a3,
                                         unsigned b0, unsigned b1) {
    asm volatile(
        "mma.sync.aligned.m16n8k8.row.col.f32.tf32.tf32.f32 "
        "{%0,%1,%2,%3},{%4,%5,%6,%7},{%8,%9},{%0,%1,%2,%3};"
        : "+f"(c[0]), "+f"(c[1]), "+f"(c[2]), "+f"(c[3])
        : "r"(a0), "r"(a1), "r"(a2), "r"(a3), "r"(b0), "r"(b1));
}

// ---------------- GEMM1 (tensor core, tf32): h1' = fp16(dinv * (x @ W1^T)) ----------------
#define GPAD 68
__global__ void gemm1_kernel(const float* __restrict__ X, const float* __restrict__ W) {
    __shared__ unsigned As[64 * GPAD];   // A tile (tf32 bits), [node_local][k]
    __shared__ unsigned Ws[64 * GPAD];   // W tile (tf32 bits), [out_ch][k]

    const int tid  = threadIdx.x;
    const int warp = tid >> 5, lane = tid & 31;
    const int g    = lane >> 2, tig = lane & 3;
    const int m0   = (warp >> 1) * 16;
    const int nb   = (warp & 1) * 32;
    const int node0 = blockIdx.x * 64;

    float c[4][4];
    #pragma unroll
    for (int nt = 0; nt < 4; nt++)
        #pragma unroll
        for (int j = 0; j < 4; j++) c[nt][j] = 0.f;

    #pragma unroll
    for (int kt = 0; kt < IN_DIM; kt += 64) {
        #pragma unroll
        for (int i = tid; i < 64 * 64; i += 256) {
            int r = i >> 6, k = i & 63;
            int node = node0 + r;
            if (node > N_NODES - 1) node = N_NODES - 1;
            As[r * GPAD + k] = f2tf(X[node * IN_DIM + kt + k]);
        }
        #pragma unroll
        for (int i = tid; i < 64 * 64; i += 256) {
            int r = i >> 6, k = i & 63;
            Ws[r * GPAD + k] = f2tf(W[r * IN_DIM + kt + k]);
        }
        __syncthreads();

        #pragma unroll
        for (int ks = 0; ks < 8; ks++) {
            int k0 = ks * 8;
            unsigned a0 = As[(m0 + g)     * GPAD + k0 + tig];
            unsigned a1 = As[(m0 + g + 8) * GPAD + k0 + tig];
            unsigned a2 = As[(m0 + g)     * GPAD + k0 + tig + 4];
            unsigned a3 = As[(m0 + g + 8) * GPAD + k0 + tig + 4];
            #pragma unroll
            for (int nt = 0; nt < 4; nt++) {
                int n0 = nb + nt * 8;
                unsigned b0 = Ws[(n0 + g) * GPAD + k0 + tig];
                unsigned b1 = Ws[(n0 + g) * GPAD + k0 + tig + 4];
                mma_tf32(c[nt], a0, a1, a2, a3, b0, b1);
            }
        }
        __syncthreads();
    }

    int nodeA = node0 + m0 + g;
    int nodeB = nodeA + 8;
    int colh  = (nb >> 1) + tig;
    if (nodeA < N_NODES) {
        float di = g_dinv[nodeA];
        #pragma unroll
        for (int nt = 0; nt < 4; nt++)
            g_h1h[nodeA * 32 + colh + nt * 4] = __floats2half2_rn(c[nt][0] * di, c[nt][1] * di);
    }
    if (nodeB < N_NODES) {
        float di = g_dinv[nodeB];
        #pragma unroll
        for (int nt = 0; nt < 4; nt++)
            g_h1h[nodeB * 32 + colh + nt * 4] = __floats2half2_rn(c[nt][2] * di, c[nt][3] * di);
    }
}

// ---------------- agg1: 4 edges per warp-instruction, fused layer-2 fold ----------------
__global__ void agg1_kernel(const float* __restrict__ b1) {
    int warp = threadIdx.x >> 5, lane = threadIdx.x & 31;
    int node = blockIdx.x * 8 + warp;
    if (node >= N_NODES) return;

    const int g = lane >> 3, c = lane & 7;
    const uint4* __restrict__ h4 = (const uint4*)g_h1h;   // 8 channels per uint4

    int rbeg = g_rowptr[node];
    int rend = g_rowptr[node + 1];

    float acc[8];
    #pragma unroll
    for (int j = 0; j < 8; j++) acc[j] = 0.f;

    for (int eb = rbeg; eb < rend; eb += 4) {
        int e = eb + g;
        if (e < rend) {
            int s = g_csr[e];
            uint4 v = h4[s * 8 + c];
            const __half2* hp = (const __half2*)&v;
            #pragma unroll
            for (int j = 0; j < 4; j++) {
                float2 f = __half22float2(hp[j]);
                acc[2 * j]     += f.x;
                acc[2 * j + 1] += f.y;
            }
        }
    }
    #pragma unroll
    for (int j = 0; j < 8; j++) {
        acc[j] += __shfl_xor_sync(0xffffffffu, acc[j], 8);
        acc[j] += __shfl_xor_sync(0xffffffffu, acc[j], 16);
    }
    {
        uint4 v = h4[node * 8 + c];
        const __half2* hp = (const __half2*)&v;
        #pragma unroll
        for (int j = 0; j < 4; j++) {
            float2 f = __half22float2(hp[j]);
            acc[2 * j]     += f.x;
            acc[2 * j + 1] += f.y;
        }
    }

    float di = g_dinv[node];
    float4 bb0 = ((const float4*)b1)[c * 2];
    float4 bb1 = ((const float4*)b1)[c * 2 + 1];
    float4 wv0 = ((const float4*)g_w)[c * 2];
    float4 wv1 = ((const float4*)g_w)[c * 2 + 1];
    float bb[8] = {bb0.x, bb0.y, bb0.z, bb0.w, bb1.x, bb1.y, bb1.z, bb1.w};
    float wv[8] = {wv0.x, wv0.y, wv0.z, wv0.w, wv1.x, wv1.y, wv1.z, wv1.w};

    float p = 0.f;
    #pragma unroll
    for (int j = 0; j < 8; j++) {
        float a = fmaxf(fmaf(di, acc[j], bb[j]), 0.f);
        p = fmaf(a, wv[j], p);
    }
    p += __shfl_xor_sync(0xffffffffu, p, 1);
    p += __shfl_xor_sync(0xffffffffu, p, 2);
    p += __shfl_xor_sync(0xffffffffu, p, 4);
    if (lane == 0) g_z[node] = di * p;           // z' = dinv * (a1 . w)
}

// ---------------- agg2 (scalar): out[d] = dinv_d*(sum_s z'[s] + z'[d]) + cb ----------------
__global__ void agg2_kernel(float* __restrict__ out) {
    int warp = threadIdx.x >> 5, lane = threadIdx.x & 31;
    int node = blockIdx.x * 8 + warp;
    if (node >= N_NODES) return;

    int rbeg = g_rowptr[node];
    int rend = g_rowptr[node + 1];
    float acc = 0.f;
    for (int e = rbeg + lane; e < rend; e += 32) {
        acc += g_z[g_csr[e]];
    }
    #pragma unroll
    for (int o = 16; o > 0; o >>= 1) acc += __shfl_xor_sync(0xffffffffu, acc, o);
    if (lane == 0) out[node] = g_dinv[node] * (acc + g_z[node]) + g_cb;
}

// ---------------- launch ----------------
extern "C" void kernel_launch(void* const* d_in, const int* in_sizes, int n_in,
                              void* d_out, int out_size) {
    const float* x  = (const float*)d_in[0];
    const void*  ei = d_in[1];                 // int32 or int64, probed on device
    const float* W1 = (const float*)d_in[2];
    const float* b1 = (const float*)d_in[3];
    const float* W2 = (const float*)d_in[4];
    const float* b2 = (const float*)d_in[5];
    const float* Wc = (const float*)d_in[6];
    const float* bc = (const float*)d_in[7];
    float* out = (float*)d_out;

    // optional second branch for gemm1 || scatter overlap (event fork/join;
    // standard capture-safe pattern). Falls back to serial on any failure.
    cudaStream_t s2 = 0;
    cudaEvent_t evF = 0, evJ = 0;
    bool forked = (cudaStreamCreateWithFlags(&s2, cudaStreamNonBlocking) == cudaSuccess);
    if (forked) forked = (cudaEventCreateWithFlags(&evF, cudaEventDisableTiming) == cudaSuccess);
    if (forked) forked = (cudaEventCreateWithFlags(&evJ, cudaEventDisableTiming) == cudaSuccess);

    prep_kernel <<<PREP_NB + 2, 256>>>((const unsigned*)ei, W2, b2, Wc, bc);
    hist_kernel <<<N_EDGES / 1024, 256>>>(ei);
    scan1_kernel<<<SCAN_NB, SCAN_B>>>();
    scan2_kernel<<<1, 256>>>();
    scan3_kernel<<<(N_NODES + 511) / 512, 512>>>();

    if (forked) {
        cudaEventRecord(evF, 0);
        cudaStreamWaitEvent(s2, evF, 0);
        gemm1_kernel<<<(N_NODES + 63) / 64, 256, 0, s2>>>(x, W1);   // branch A
        scatter_kernel<<<N_EDGES / 1024, 256>>>(ei);                // branch B (origin)
        cudaEventRecord(evJ, s2);
        cudaStreamWaitEvent(0, evJ, 0);                             // join
    } else {
        scatter_kernel<<<N_EDGES / 1024, 256>>>(ei);
        gemm1_kernel<<<(N_NODES + 63) / 64, 256>>>(x, W1);
    }

    agg1_kernel<<<(N_NODES + 7) / 8, 256>>>(b1);
    agg2_kernel<<<(N_NODES + 7) / 8, 256>>>(out);
    // note: stream/event objects intentionally not destroyed here — destroying
    // capture-joined objects during active capture is illegal; kernel_launch is
    // invoked only a handful of times (correctness + capture), so the host-side
    // leak is bounded and device memory is untouched.
}

// round 9
// speedup vs baseline: 1.3064x; 1.3064x over previous
#include <cuda_runtime.h>
#include <cuda_fp16.h>

#define N_NODES 100000
#define N_EDGES 3200000
#define IN_DIM  128
#define HID     64

#define SCAN_B  512
#define SCAN_NB ((N_NODES + SCAN_B - 1) / SCAN_B)   // 196
#define PREP_NB ((N_NODES + 255) / 256)             // 391

// ---------------- scratch (device globals; no allocation allowed) ----------------
__device__ int     g_is64;                  // 1 if edge_index is int64, 0 if int32
__device__ int     g_deg[N_NODES];
__device__ float   g_dinv[N_NODES];
__device__ int     g_rowptr[N_NODES + 1];
__device__ int     g_cursor[N_NODES];
__device__ int     g_scan[N_NODES];
__device__ int     g_bsum[SCAN_NB];
__device__ int     g_boff[SCAN_NB];
__device__ int     g_csr[N_EDGES];          // src index only
__device__ __half2 g_h1h[N_NODES * (HID/2)];// h1' = dinv * (x @ W1^T), fp16
__device__ float   g_z[N_NODES];            // z'  = dinv * (a1 . w)
__device__ float   g_w[HID];                // w = W2^T @ Wc
__device__ float   g_cb;                    // b2.Wc + bc

// ---------------- prep: deg init + dtype probe + classifier fold (one launch) ----------------
__global__ void prep_kernel(const unsigned* __restrict__ ei32,
                            const float* __restrict__ W2, const float* __restrict__ b2,
                            const float* __restrict__ Wc, const float* __restrict__ bc) {
    int b = blockIdx.x, tid = threadIdx.x;
    if (b < PREP_NB) {
        int i = b * 256 + tid;
        if (i < N_NODES) g_deg[i] = 1;          // self-loop counts as 1
    } else if (b == PREP_NB) {
        if (tid == 0) {
            // int64 ids in [0,100000) => every odd 32-bit word is 0.
            unsigned o = 0;
            #pragma unroll
            for (int i = 1; i < 128; i += 2) o |= ei32[i];
            g_is64 = (o == 0) ? 1 : 0;
        }
    } else {
        if (tid < HID) {
            float s = 0.f;
            #pragma unroll
            for (int j = 0; j < HID; j++) s = fmaf(Wc[j], W2[j * HID + tid], s);
            g_w[tid] = s;
            if (tid == 0) {
                float c = bc[0];
                #pragma unroll
                for (int j = 0; j < HID; j++) c = fmaf(b2[j], Wc[j], c);
                g_cb = c;
            }
        }
    }
}

__device__ __forceinline__ int edge_at(const void* ei, long long idx) {
    if (g_is64) return (int)((const long long*)ei)[idx];
    return ((const int*)ei)[idx];
}

// ---------------- dst-degree histogram (1 edge/thread: max atomic MLP) ----------------
__global__ void hist_kernel(const void* __restrict__ ei) {
    int e = blockIdx.x * blockDim.x + threadIdx.x;
    if (e < N_EDGES) {
        int d = edge_at(ei, (long long)N_EDGES + e);
        atomicAdd(&g_deg[d], 1);
    }
}

// ---------------- parallel 3-phase exclusive scan of (deg-1) ----------------
__global__ void scan1_kernel() {
    __shared__ int wsum[16];
    const int tid  = threadIdx.x;
    const int lane = tid & 31, warp = tid >> 5;
    const int i = blockIdx.x * SCAN_B + tid;
    int v = (i < N_NODES) ? (g_deg[i] - 1) : 0;
    int s = v;
    #pragma unroll
    for (int o = 1; o < 32; o <<= 1) {
        int t = __shfl_up_sync(0xffffffffu, s, o);
        if (lane >= o) s += t;
    }
    if (lane == 31) wsum[warp] = s;
    __syncthreads();
    if (warp == 0) {
        int ws = (lane < 16) ? wsum[lane] : 0;
        #pragma unroll
        for (int o = 1; o < 16; o <<= 1) {
            int t = __shfl_up_sync(0xffffffffu, ws, o);
            if (lane >= o) ws += t;
        }
        if (lane < 16) wsum[lane] = ws;
    }
    __syncthreads();
    int excl = s - v + (warp ? wsum[warp - 1] : 0);
    if (i < N_NODES) g_scan[i] = excl;
    if (tid == SCAN_B - 1) g_bsum[blockIdx.x] = excl + v;
}

__global__ void scan2_kernel() {       // 1 block, 256 threads (>=196)
    __shared__ int sh[256];
    const int t = threadIdx.x;
    int v0 = (t < SCAN_NB) ? g_bsum[t] : 0;
    sh[t] = v0;
    __syncthreads();
    #pragma unroll
    for (int o = 1; o < 256; o <<= 1) {
        int v = (t >= o) ? sh[t - o] : 0;
        __syncthreads();
        sh[t] += v;
        __syncthreads();
    }
    if (t < SCAN_NB) g_boff[t] = sh[t] - v0;
}

__global__ void scan3_kernel() {
    int i = blockIdx.x * blockDim.x + threadIdx.x;
    if (i < N_NODES) {
        int off = g_scan[i] + g_boff[i / SCAN_B];
        g_rowptr[i] = off;
        g_cursor[i] = off;
        g_dinv[i]   = rsqrtf((float)g_deg[i]);
    }
    if (i == 0) g_rowptr[N_NODES] = N_EDGES;   // sum(deg-1) == E
}

// ---------------- counting-sort scatter (1 edge/thread: max atomic MLP) ----------------
__global__ void scatter_kernel(const void* __restrict__ ei) {
    int e = blockIdx.x * blockDim.x + threadIdx.x;
    if (e < N_EDGES) {
        int s = edge_at(ei, e);
        int d = edge_at(ei, (long long)N_EDGES + e);
        int pos = atomicAdd(&g_cursor[d], 1);
        g_csr[pos] = s;
    }
}

// ---------------- tf32 helpers ----------------
__device__ __forceinline__ unsigned f2tf(float f) {
    unsigned u;
    asm("cvt.rna.tf32.f32 %0, %1;" : "=r"(u) : "f"(f));
    return u;
}

__device__ __forceinline__ void mma_tf32(float* c,
                                         unsigned a0, unsigned a1, unsigned a2, unsigned a3,
                                         unsigned b0, unsigned b1) {
    asm volatile(
        "mma.sync.aligned.m16n8k8.row.col.f32.tf32.tf32.f32 "
        "{%0,%1,%2,%3},{%4,%5,%6,%7},{%8,%9},{%0,%1,%2,%3};"
        : "+f"(c[0]), "+f"(c[1]), "+f"(c[2]), "+f"(c[3])
        : "r"(a0), "r"(a1), "r"(a2), "r"(a3), "r"(b0), "r"(b1));
}

// ---------------- GEMM1 (tensor core, tf32): h1' = fp16(dinv * (x @ W1^T)) ----------------
#define GPAD 68
__global__ void gemm1_kernel(const float* __restrict__ X, const float* __restrict__ W) {
    __shared__ unsigned As[64 * GPAD];   // A tile (tf32 bits), [node_local][k]
    __shared__ unsigned Ws[64 * GPAD];   // W tile (tf32 bits), [out_ch][k]

    const int tid  = threadIdx.x;
    const int warp = tid >> 5, lane = tid & 31;
    const int g    = lane >> 2, tig = lane & 3;
    const int m0   = (warp >> 1) * 16;
    const int nb   = (warp & 1) * 32;
    const int node0 = blockIdx.x * 64;

    float c[4][4];
    #pragma unroll
    for (int nt = 0; nt < 4; nt++)
        #pragma unroll
        for (int j = 0; j < 4; j++) c[nt][j] = 0.f;

    #pragma unroll
    for (int kt = 0; kt < IN_DIM; kt += 64) {
        #pragma unroll
        for (int i = tid; i < 64 * 64; i += 256) {
            int r = i >> 6, k = i & 63;
            int node = node0 + r;
            if (node > N_NODES - 1) node = N_NODES - 1;
            As[r * GPAD + k] = f2tf(X[node * IN_DIM + kt + k]);
        }
        #pragma unroll
        for (int i = tid; i < 64 * 64; i += 256) {
            int r = i >> 6, k = i & 63;
            Ws[r * GPAD + k] = f2tf(W[r * IN_DIM + kt + k]);
        }
        __syncthreads();

        #pragma unroll
        for (int ks = 0; ks < 8; ks++) {
            int k0 = ks * 8;
            unsigned a0 = As[(m0 + g)     * GPAD + k0 + tig];
            unsigned a1 = As[(m0 + g + 8) * GPAD + k0 + tig];
            unsigned a2 = As[(m0 + g)     * GPAD + k0 + tig + 4];
            unsigned a3 = As[(m0 + g + 8) * GPAD + k0 + tig + 4];
            #pragma unroll
            for (int nt = 0; nt < 4; nt++) {
                int n0 = nb + nt * 8;
                unsigned b0 = Ws[(n0 + g) * GPAD + k0 + tig];
                unsigned b1 = Ws[(n0 + g) * GPAD + k0 + tig + 4];
                mma_tf32(c[nt], a0, a1, a2, a3, b0, b1);
            }
        }
        __syncthreads();
    }

    int nodeA = node0 + m0 + g;
    int nodeB = nodeA + 8;
    int colh  = (nb >> 1) + tig;
    if (nodeA < N_NODES) {
        float di = g_dinv[nodeA];
        #pragma unroll
        for (int nt = 0; nt < 4; nt++)
            g_h1h[nodeA * 32 + colh + nt * 4] = __floats2half2_rn(c[nt][0] * di, c[nt][1] * di);
    }
    if (nodeB < N_NODES) {
        float di = g_dinv[nodeB];
        #pragma unroll
        for (int nt = 0; nt < 4; nt++)
            g_h1h[nodeB * 32 + colh + nt * 4] = __floats2half2_rn(c[nt][2] * di, c[nt][3] * di);
    }
}

// ---------------- agg1: 4 edges per warp-instruction, fused layer-2 fold ----------------
__global__ void agg1_kernel(const float* __restrict__ b1) {
    int warp = threadIdx.x >> 5, lane = threadIdx.x & 31;
    int node = blockIdx.x * 8 + warp;
    if (node >= N_NODES) return;

    const int g = lane >> 3, c = lane & 7;
    const uint4* __restrict__ h4 = (const uint4*)g_h1h;   // 8 channels per uint4

    int rbeg = g_rowptr[node];
    int rend = g_rowptr[node + 1];

    float acc[8];
    #pragma unroll
    for (int j = 0; j < 8; j++) acc[j] = 0.f;

    for (int eb = rbeg; eb < rend; eb += 4) {
        int e = eb + g;
        if (e < rend) {
            int s = g_csr[e];
            uint4 v = h4[s * 8 + c];
            const __half2* hp = (const __half2*)&v;
            #pragma unroll
            for (int j = 0; j < 4; j++) {
                float2 f = __half22float2(hp[j]);
                acc[2 * j]     += f.x;
                acc[2 * j + 1] += f.y;
            }
        }
    }
    #pragma unroll
    for (int j = 0; j < 8; j++) {
        acc[j] += __shfl_xor_sync(0xffffffffu, acc[j], 8);
        acc[j] += __shfl_xor_sync(0xffffffffu, acc[j], 16);
    }
    {
        uint4 v = h4[node * 8 + c];
        const __half2* hp = (const __half2*)&v;
        #pragma unroll
        for (int j = 0; j < 4; j++) {
            float2 f = __half22float2(hp[j]);
            acc[2 * j]     += f.x;
            acc[2 * j + 1] += f.y;
        }
    }

    float di = g_dinv[node];
    float4 bb0 = ((const float4*)b1)[c * 2];
    float4 bb1 = ((const float4*)b1)[c * 2 + 1];
    float4 wv0 = ((const float4*)g_w)[c * 2];
    float4 wv1 = ((const float4*)g_w)[c * 2 + 1];
    float bb[8] = {bb0.x, bb0.y, bb0.z, bb0.w, bb1.x, bb1.y, bb1.z, bb1.w};
    float wv[8] = {wv0.x, wv0.y, wv0.z, wv0.w, wv1.x, wv1.y, wv1.z, wv1.w};

    float p = 0.f;
    #pragma unroll
    for (int j = 0; j < 8; j++) {
        float a = fmaxf(fmaf(di, acc[j], bb[j]), 0.f);
        p = fmaf(a, wv[j], p);
    }
    p += __shfl_xor_sync(0xffffffffu, p, 1);
    p += __shfl_xor_sync(0xffffffffu, p, 2);
    p += __shfl_xor_sync(0xffffffffu, p, 4);
    if (lane == 0) g_z[node] = di * p;           // z' = dinv * (a1 . w)
}

// ---------------- agg2 (scalar): out[d] = dinv_d*(sum_s z'[s] + z'[d]) + cb ----------------
__global__ void agg2_kernel(float* __restrict__ out) {
    int warp = threadIdx.x >> 5, lane = threadIdx.x & 31;
    int node = blockIdx.x * 8 + warp;
    if (node >= N_NODES) return;

    int rbeg = g_rowptr[node];
    int rend = g_rowptr[node + 1];
    float acc = 0.f;
    for (int e = rbeg + lane; e < rend; e += 32) {
        acc += g_z[g_csr[e]];
    }
    #pragma unroll
    for (int o = 16; o > 0; o >>= 1) acc += __shfl_xor_sync(0xffffffffu, acc, o);
    if (lane == 0) out[node] = g_dinv[node] * (acc + g_z[node]) + g_cb;
}

// ---------------- launch (serial single stream; fork/join was a proven loss) ----------------
extern "C" void kernel_launch(void* const* d_in, const int* in_sizes, int n_in,
                              void* d_out, int out_size) {
    const float* x  = (const float*)d_in[0];
    const void*  ei = d_in[1];                 // int32 or int64, probed on device
    const float* W1 = (const float*)d_in[2];
    const float* b1 = (const float*)d_in[3];
    const float* W2 = (const float*)d_in[4];
    const float* b2 = (const float*)d_in[5];
    const float* Wc = (const float*)d_in[6];
    const float* bc = (const float*)d_in[7];
    float* out = (float*)d_out;

    prep_kernel   <<<PREP_NB + 2, 256>>>((const unsigned*)ei, W2, b2, Wc, bc);
    hist_kernel   <<<N_EDGES / 256, 256>>>(ei);
    scan1_kernel  <<<SCAN_NB, SCAN_B>>>();
    scan2_kernel  <<<1, 256>>>();
    scan3_kernel  <<<(N_NODES + 511) / 512, 512>>>();
    scatter_kernel<<<N_EDGES / 256, 256>>>(ei);
    gemm1_kernel  <<<(N_NODES + 63) / 64, 256>>>(x, W1);
    agg1_kernel   <<<(N_NODES + 7) / 8, 256>>>(b1);
    agg2_kernel   <<<(N_NODES + 7) / 8, 256>>>(out);
}